// round 1
// baseline (speedup 1.0000x reference)
#include <cuda_runtime.h>
#include <math.h>

#define NR 8192      // rays
#define SS 128       // samples per ray
#define HID 64

// Scratch: [s][ray][4] = (sigma, r, g, b)  -- 16 MB static device array (no allocs allowed)
__device__ float4 g_scr[NR * SS];
__device__ float g_dt;

// ---------------------------------------------------------------------------
// Deterministic reduction: dt = mean(tmax - tmin) / S
// ---------------------------------------------------------------------------
__global__ void dt_kernel(const float* __restrict__ tmin, const float* __restrict__ tmax) {
    __shared__ float red[1024];
    int t = threadIdx.x;
    float s = 0.f;
    for (int i = t; i < NR; i += 1024) s += tmax[i] - tmin[i];
    red[t] = s;
    __syncthreads();
    for (int k = 512; k > 0; k >>= 1) {
        if (t < k) red[t] += red[t + k];
        __syncthreads();
    }
    if (t == 0) g_dt = red[0] / (float)(NR * SS);
}

// ---------------------------------------------------------------------------
// rank-1 accumulate: h[0..63] += v * w[0..63]   (w in smem, warp-uniform -> broadcast)
// ---------------------------------------------------------------------------
__device__ __forceinline__ void acc64(float (&h)[HID], float v, const float* __restrict__ w) {
#pragma unroll
    for (int j = 0; j < HID; j += 4) {
        float4 wv = *reinterpret_cast<const float4*>(w + j);
        h[j + 0] = fmaf(v, wv.x, h[j + 0]);
        h[j + 1] = fmaf(v, wv.y, h[j + 1]);
        h[j + 2] = fmaf(v, wv.z, h[j + 2]);
        h[j + 3] = fmaf(v, wv.w, h[j + 3]);
    }
}

// ---------------------------------------------------------------------------
// Per-sample MLP kernel: one thread per (ray, sample); sample-major thread order
// gid = s*NR + ray  -> coalesced ray loads + coalesced scratch writes.
// ---------------------------------------------------------------------------
__global__ __launch_bounds__(256)
void mlp_kernel(const float* __restrict__ orig, const float* __restrict__ dirs,
                const float* __restrict__ tmin, const float* __restrict__ tmax,
                const float* __restrict__ W1, const float* __restrict__ b1,
                const float* __restrict__ W2, const float* __restrict__ b2,
                const float* __restrict__ V1, const float* __restrict__ c1,
                const float* __restrict__ V2, const float* __restrict__ c2) {
    __shared__ __align__(16) float sW1[63 * 64];
    __shared__ __align__(16) float sb1[64];
    __shared__ __align__(16) float sW2[64 * 16];
    __shared__ __align__(16) float sb2[16];
    __shared__ __align__(16) float sV1[42 * 64];
    __shared__ __align__(16) float sc1[64];
    __shared__ __align__(16) float sV2[64 * 3];
    __shared__ __align__(16) float sc2[4];

    const int t = threadIdx.x;
    for (int i = t; i < 63 * 64; i += 256) sW1[i] = W1[i];
    for (int i = t; i < 64; i += 256)      sb1[i] = b1[i];
    for (int i = t; i < 64 * 16; i += 256) sW2[i] = W2[i];
    for (int i = t; i < 16; i += 256)      sb2[i] = b2[i];
    for (int i = t; i < 42 * 64; i += 256) sV1[i] = V1[i];
    for (int i = t; i < 64; i += 256)      sc1[i] = c1[i];
    for (int i = t; i < 64 * 3; i += 256)  sV2[i] = V2[i];
    if (t < 3) sc2[t] = c2[t];
    __syncthreads();

    const int gid = blockIdx.x * 256 + t;
    const int ray = gid & (NR - 1);
    const int s   = gid >> 13;   // NR = 2^13

    const float ox = orig[ray * 3 + 0], oy = orig[ray * 3 + 1], oz = orig[ray * 3 + 2];
    const float dx = dirs[ray * 3 + 0], dy = dirs[ray * 3 + 1], dz = dirs[ray * 3 + 2];
    const float t0 = tmin[ray], t1 = tmax[ray];

    const float tu = (float)s * (1.0f / (SS - 1));   // linspace(0,1,S)
    const float tt = t0 + tu * (t1 - t0);
    const float px = fmaf(dx, tt, ox);
    const float py = fmaf(dy, tt, oy);
    const float pz = fmaf(dz, tt, oz);

    // -------- MLP 1: enc(63) -> h(64) ----------------------------------
    float h[HID];
#pragma unroll
    for (int j = 0; j < HID; j++) h[j] = sb1[j];

    acc64(h, px, sW1 + 0 * 64);
    acc64(h, py, sW1 + 1 * 64);
    acc64(h, pz, sW1 + 2 * 64);

    float fr = 1.0f;
#pragma unroll 1
    for (int i = 0; i < 10; i++) {
        float sx, cx, sy, cy, sz, cz;
        sincosf(fr * px, &sx, &cx);
        sincosf(fr * py, &sy, &cy);
        sincosf(fr * pz, &sz, &cz);
        const float* base = sW1 + (3 + 6 * i) * 64;
        acc64(h, sx, base + 0 * 64);
        acc64(h, sy, base + 1 * 64);
        acc64(h, sz, base + 2 * 64);
        acc64(h, cx, base + 3 * 64);
        acc64(h, cy, base + 4 * 64);
        acc64(h, cz, base + 5 * 64);
        fr *= 2.0f;
    }

    // -------- layer 2: relu(h) @ W2 + b2 -> out(16) --------------------
    float out[16];
#pragma unroll
    for (int k = 0; k < 16; k++) out[k] = sb2[k];
#pragma unroll
    for (int j = 0; j < HID; j++) {
        const float hv = fmaxf(h[j], 0.0f);
        const float4 w0 = *reinterpret_cast<const float4*>(sW2 + j * 16 + 0);
        const float4 w1 = *reinterpret_cast<const float4*>(sW2 + j * 16 + 4);
        const float4 w2 = *reinterpret_cast<const float4*>(sW2 + j * 16 + 8);
        const float4 w3 = *reinterpret_cast<const float4*>(sW2 + j * 16 + 12);
        out[0]  = fmaf(hv, w0.x, out[0]);  out[1]  = fmaf(hv, w0.y, out[1]);
        out[2]  = fmaf(hv, w0.z, out[2]);  out[3]  = fmaf(hv, w0.w, out[3]);
        out[4]  = fmaf(hv, w1.x, out[4]);  out[5]  = fmaf(hv, w1.y, out[5]);
        out[6]  = fmaf(hv, w1.z, out[6]);  out[7]  = fmaf(hv, w1.w, out[7]);
        out[8]  = fmaf(hv, w2.x, out[8]);  out[9]  = fmaf(hv, w2.y, out[9]);
        out[10] = fmaf(hv, w2.z, out[10]); out[11] = fmaf(hv, w2.w, out[11]);
        out[12] = fmaf(hv, w3.x, out[12]); out[13] = fmaf(hv, w3.y, out[13]);
        out[14] = fmaf(hv, w3.z, out[14]); out[15] = fmaf(hv, w3.w, out[15]);
    }

    const float sigma = fmaxf(out[0], 0.0f);

    // -------- MLP 2: [rgb_feat(15), vd_enc(27)] -> g(64) ---------------
    const float nrm = sqrtf(dx * dx + dy * dy + dz * dz) + 1e-8f;
    const float inv = 1.0f / nrm;
    const float vx = dx * inv, vy = dy * inv, vz = dz * inv;

    float g[HID];
#pragma unroll
    for (int j = 0; j < HID; j++) g[j] = sc1[j];

#pragma unroll
    for (int f = 0; f < 15; f++) acc64(g, out[1 + f], sV1 + f * 64);

    acc64(g, vx, sV1 + 15 * 64);
    acc64(g, vy, sV1 + 16 * 64);
    acc64(g, vz, sV1 + 17 * 64);

    float fv = 1.0f;
#pragma unroll 1
    for (int i = 0; i < 4; i++) {
        float sx, cx, sy, cy, sz, cz;
        sincosf(fv * vx, &sx, &cx);
        sincosf(fv * vy, &sy, &cy);
        sincosf(fv * vz, &sz, &cz);
        const float* base = sV1 + (18 + 6 * i) * 64;
        acc64(g, sx, base + 0 * 64);
        acc64(g, sy, base + 1 * 64);
        acc64(g, sz, base + 2 * 64);
        acc64(g, cx, base + 3 * 64);
        acc64(g, cy, base + 4 * 64);
        acc64(g, cz, base + 5 * 64);
        fv *= 2.0f;
    }

    // -------- layer 4: relu(g) @ V2 + c2 -> rgb(3), sigmoid ------------
    float r0 = sc2[0], r1 = sc2[1], r2 = sc2[2];
#pragma unroll
    for (int j = 0; j < HID; j++) {
        const float gv = fmaxf(g[j], 0.0f);
        r0 = fmaf(gv, sV2[j * 3 + 0], r0);
        r1 = fmaf(gv, sV2[j * 3 + 1], r1);
        r2 = fmaf(gv, sV2[j * 3 + 2], r2);
    }
    r0 = 1.0f / (1.0f + expf(-r0));
    r1 = 1.0f / (1.0f + expf(-r1));
    r2 = 1.0f / (1.0f + expf(-r2));

    g_scr[s * NR + ray] = make_float4(sigma, r0, r1, r2);
}

// ---------------------------------------------------------------------------
// Per-ray transmittance scan with early-stop semantics of the reference.
// ---------------------------------------------------------------------------
__global__ __launch_bounds__(256)
void scan_kernel(float* __restrict__ outp) {
    const int ray = blockIdx.x * 256 + threadIdx.x;
    if (ray >= NR) return;
    const float dt = g_dt;

    float T = 1.0f, r = 0.f, g = 0.f, b = 0.f;
#pragma unroll 4
    for (int s = 0; s < SS; s++) {
        const float4 v = g_scr[s * NR + ray];
        const float alpha = 1.0f - expf(-v.x * dt);
        const bool active = T > 1e-4f;   // active based on T_excl (pre-update T)
        const float w = active ? T * alpha : 0.0f;
        r = fmaf(w, v.y, r);
        g = fmaf(w, v.z, g);
        b = fmaf(w, v.w, b);
        if (active) T *= (1.0f - alpha);
    }
    outp[ray * 3 + 0] = r;
    outp[ray * 3 + 1] = g;
    outp[ray * 3 + 2] = b;
    outp[3 * NR + ray] = T;
}

// ---------------------------------------------------------------------------
extern "C" void kernel_launch(void* const* d_in, const int* in_sizes, int n_in,
                              void* d_out, int out_size) {
    const float* orig = (const float*)d_in[0];
    const float* dirs = (const float*)d_in[1];
    const float* tmin = (const float*)d_in[2];
    const float* tmax = (const float*)d_in[3];
    const float* W1   = (const float*)d_in[4];
    const float* b1   = (const float*)d_in[5];
    const float* W2   = (const float*)d_in[6];
    const float* b2   = (const float*)d_in[7];
    const float* V1   = (const float*)d_in[8];
    const float* c1   = (const float*)d_in[9];
    const float* V2   = (const float*)d_in[10];
    const float* c2   = (const float*)d_in[11];

    dt_kernel<<<1, 1024>>>(tmin, tmax);
    mlp_kernel<<<(NR * SS) / 256, 256>>>(orig, dirs, tmin, tmax,
                                         W1, b1, W2, b2, V1, c1, V2, c2);
    scan_kernel<<<NR / 256, 256>>>((float*)d_out);
}

// round 2
// speedup vs baseline: 1.0887x; 1.0887x over previous
#include <cuda_runtime.h>
#include <math.h>

#define NR 8192      // rays
#define SS 128       // samples per ray
#define HID 64

typedef unsigned long long u64;

// Scratch: [s][ray][4] = (sigma, r, g, b)  -- 16 MB static device array
__device__ float4 g_scr[NR * SS];
__device__ float g_dt;

// ---------------------------------------------------------------------------
// packed f32x2 helpers
// ---------------------------------------------------------------------------
__device__ __forceinline__ u64 pk(float a, float b) {
    u64 r; asm("mov.b64 %0,{%1,%2};" : "=l"(r) : "f"(a), "f"(b)); return r;
}
__device__ __forceinline__ void upk(u64 v, float& a, float& b) {
    asm("mov.b64 {%0,%1},%2;" : "=f"(a), "=f"(b) : "l"(v));
}
__device__ __forceinline__ u64 f2fma(u64 a, u64 b, u64 c) {
    u64 d; asm("fma.rn.f32x2 %0,%1,%2,%3;" : "=l"(d) : "l"(a), "l"(b), "l"(c)); return d;
}

// rank-1 accumulate, packed: H[0..31] (=64 floats) += vv * w[0..63]
__device__ __forceinline__ void acc64p(u64 (&H)[32], u64 vv, const float* __restrict__ w) {
#pragma unroll
    for (int k = 0; k < 16; k++) {
        const ulonglong2 wp = *reinterpret_cast<const ulonglong2*>(w + 4 * k);
        H[2 * k + 0] = f2fma(vv, wp.x, H[2 * k + 0]);
        H[2 * k + 1] = f2fma(vv, wp.y, H[2 * k + 1]);
    }
}

// ---------------------------------------------------------------------------
// dt = mean(tmax - tmin) / S  (deterministic, fast)
// ---------------------------------------------------------------------------
__global__ __launch_bounds__(1024)
void dt_kernel(const float* __restrict__ tmin, const float* __restrict__ tmax) {
    __shared__ float red[32];
    const int t = threadIdx.x;
    const float4* a = (const float4*)tmin;
    const float4* b = (const float4*)tmax;
    float s = 0.f;
#pragma unroll
    for (int i = t; i < NR / 4; i += 1024) {
        float4 x = a[i], y = b[i];
        s += (y.x - x.x) + (y.y - x.y) + (y.z - x.z) + (y.w - x.w);
    }
#pragma unroll
    for (int o = 16; o > 0; o >>= 1) s += __shfl_down_sync(0xffffffffu, s, o);
    if ((t & 31) == 0) red[t >> 5] = s;
    __syncthreads();
    if (t < 32) {
        float v = red[t];
#pragma unroll
        for (int o = 16; o > 0; o >>= 1) v += __shfl_down_sync(0xffffffffu, v, o);
        if (t == 0) g_dt = v / (float)(NR * SS);
    }
}

// ---------------------------------------------------------------------------
// Per-sample MLP kernel: one thread per (ray, sample), sample-major order.
// ---------------------------------------------------------------------------
__global__ __launch_bounds__(256)
void mlp_kernel(const float* __restrict__ orig, const float* __restrict__ dirs,
                const float* __restrict__ tmin, const float* __restrict__ tmax,
                const float* __restrict__ W1, const float* __restrict__ b1,
                const float* __restrict__ W2, const float* __restrict__ b2,
                const float* __restrict__ V1, const float* __restrict__ c1,
                const float* __restrict__ V2, const float* __restrict__ c2) {
    __shared__ __align__(16) float sW1[63 * 64];
    __shared__ __align__(16) float sb1[64];
    __shared__ __align__(16) float sW2[64 * 16];
    __shared__ __align__(16) float sb2[16];
    __shared__ __align__(16) float sV1[42 * 64];
    __shared__ __align__(16) float sc1[64];
    __shared__ __align__(16) float sV2[64 * 3];
    __shared__ __align__(16) float sc2[4];

    const int t = threadIdx.x;
    for (int i = t; i < 63 * 64; i += 256) sW1[i] = W1[i];
    for (int i = t; i < 64; i += 256)      sb1[i] = b1[i];
    for (int i = t; i < 64 * 16; i += 256) sW2[i] = W2[i];
    for (int i = t; i < 16; i += 256)      sb2[i] = b2[i];
    for (int i = t; i < 42 * 64; i += 256) sV1[i] = V1[i];
    for (int i = t; i < 64; i += 256)      sc1[i] = c1[i];
    for (int i = t; i < 64 * 3; i += 256)  sV2[i] = V2[i];
    if (t < 3) sc2[t] = c2[t];
    __syncthreads();

    const int gid = blockIdx.x * 256 + t;
    const int ray = gid & (NR - 1);
    const int s   = gid >> 13;   // NR = 2^13

    const float ox = orig[ray * 3 + 0], oy = orig[ray * 3 + 1], oz = orig[ray * 3 + 2];
    const float dx = dirs[ray * 3 + 0], dy = dirs[ray * 3 + 1], dz = dirs[ray * 3 + 2];
    const float t0 = tmin[ray], t1 = tmax[ray];

    const float tu = (float)s * (1.0f / (SS - 1));
    const float tt = t0 + tu * (t1 - t0);
    const float px = fmaf(dx, tt, ox);
    const float py = fmaf(dy, tt, oy);
    const float pz = fmaf(dz, tt, oz);

    // -------- MLP 1: enc(63) -> h(64), packed accumulators --------------
    u64 H[32];
#pragma unroll
    for (int k = 0; k < 16; k++) {
        const ulonglong2 bp = *reinterpret_cast<const ulonglong2*>(sb1 + 4 * k);
        H[2 * k + 0] = bp.x;
        H[2 * k + 1] = bp.y;
    }

    acc64p(H, pk(px, px), sW1 + 0 * 64);
    acc64p(H, pk(py, py), sW1 + 1 * 64);
    acc64p(H, pk(pz, pz), sW1 + 2 * 64);

    // double-angle ladder: one sincos per axis, 10 bands
    {
        float sx, cx, sy, cy, sz, cz;
        sincosf(px, &sx, &cx);
        sincosf(py, &sy, &cy);
        sincosf(pz, &sz, &cz);
#pragma unroll 1
        for (int i = 0; i < 10; i++) {
            const float* base = sW1 + (3 + 6 * i) * 64;
            acc64p(H, pk(sx, sx), base + 0 * 64);
            acc64p(H, pk(sy, sy), base + 1 * 64);
            acc64p(H, pk(sz, sz), base + 2 * 64);
            acc64p(H, pk(cx, cx), base + 3 * 64);
            acc64p(H, pk(cy, cy), base + 4 * 64);
            acc64p(H, pk(cz, cz), base + 5 * 64);
            // advance to next band: sin(2a)=2sc, cos(2a)=1-2s^2
            const float nsx = 2.0f * sx * cx, ncx = fmaf(-2.0f * sx, sx, 1.0f);
            const float nsy = 2.0f * sy * cy, ncy = fmaf(-2.0f * sy, sy, 1.0f);
            const float nsz = 2.0f * sz * cz, ncz = fmaf(-2.0f * sz, sz, 1.0f);
            sx = nsx; cx = ncx; sy = nsy; cy = ncy; sz = nsz; cz = ncz;
        }
    }

    // -------- layer 2: relu(h) @ W2 + b2 -> out(16), packed -------------
    u64 O[8];
#pragma unroll
    for (int k = 0; k < 4; k++) {
        const ulonglong2 bp = *reinterpret_cast<const ulonglong2*>(sb2 + 4 * k);
        O[2 * k + 0] = bp.x;
        O[2 * k + 1] = bp.y;
    }
#pragma unroll
    for (int jp = 0; jp < 32; jp++) {
        float h0, h1;
        upk(H[jp], h0, h1);
        h0 = fmaxf(h0, 0.0f);
        h1 = fmaxf(h1, 0.0f);
        const u64 v0 = pk(h0, h0), v1 = pk(h1, h1);
        const float* r0w = sW2 + (2 * jp + 0) * 16;
        const float* r1w = sW2 + (2 * jp + 1) * 16;
#pragma unroll
        for (int m = 0; m < 2; m++) {
            const ulonglong2 w0 = *reinterpret_cast<const ulonglong2*>(r0w + 8 * m);
            const ulonglong2 w1 = *reinterpret_cast<const ulonglong2*>(r1w + 8 * m);
            O[4 * m + 0] = f2fma(v0, w0.x, O[4 * m + 0]);
            O[4 * m + 1] = f2fma(v0, w0.y, O[4 * m + 1]);
            O[4 * m + 0] = f2fma(v1, w1.x, O[4 * m + 0]);
            O[4 * m + 1] = f2fma(v1, w1.y, O[4 * m + 1]);
        }
#pragma unroll
        for (int m = 0; m < 2; m++) {
            const ulonglong2 w0 = *reinterpret_cast<const ulonglong2*>(r0w + 8 * m + 4);
            const ulonglong2 w1 = *reinterpret_cast<const ulonglong2*>(r1w + 8 * m + 4);
            O[4 * m + 2] = f2fma(v0, w0.x, O[4 * m + 2]);
            O[4 * m + 3] = f2fma(v0, w0.y, O[4 * m + 3]);
            O[4 * m + 2] = f2fma(v1, w1.x, O[4 * m + 2]);
            O[4 * m + 3] = f2fma(v1, w1.y, O[4 * m + 3]);
        }
    }

    float out[16];
#pragma unroll
    for (int k = 0; k < 8; k++) upk(O[k], out[2 * k], out[2 * k + 1]);

    const float sigma = fmaxf(out[0], 0.0f);

    // -------- MLP 2: [rgb_feat(15), vd_enc(27)] -> g(64), packed --------
    const float nrm = sqrtf(dx * dx + dy * dy + dz * dz) + 1e-8f;
    const float inv = 1.0f / nrm;
    const float vx = dx * inv, vy = dy * inv, vz = dz * inv;

    u64 G[32];
#pragma unroll
    for (int k = 0; k < 16; k++) {
        const ulonglong2 bp = *reinterpret_cast<const ulonglong2*>(sc1 + 4 * k);
        G[2 * k + 0] = bp.x;
        G[2 * k + 1] = bp.y;
    }

#pragma unroll
    for (int f = 0; f < 15; f++) acc64p(G, pk(out[1 + f], out[1 + f]), sV1 + f * 64);

    acc64p(G, pk(vx, vx), sV1 + 15 * 64);
    acc64p(G, pk(vy, vy), sV1 + 16 * 64);
    acc64p(G, pk(vz, vz), sV1 + 17 * 64);

    {
        float sx, cx, sy, cy, sz, cz;
        sincosf(vx, &sx, &cx);
        sincosf(vy, &sy, &cy);
        sincosf(vz, &sz, &cz);
#pragma unroll 1
        for (int i = 0; i < 4; i++) {
            const float* base = sV1 + (18 + 6 * i) * 64;
            acc64p(G, pk(sx, sx), base + 0 * 64);
            acc64p(G, pk(sy, sy), base + 1 * 64);
            acc64p(G, pk(sz, sz), base + 2 * 64);
            acc64p(G, pk(cx, cx), base + 3 * 64);
            acc64p(G, pk(cy, cy), base + 4 * 64);
            acc64p(G, pk(cz, cz), base + 5 * 64);
            const float nsx = 2.0f * sx * cx, ncx = fmaf(-2.0f * sx, sx, 1.0f);
            const float nsy = 2.0f * sy * cy, ncy = fmaf(-2.0f * sy, sy, 1.0f);
            const float nsz = 2.0f * sz * cz, ncz = fmaf(-2.0f * sz, sz, 1.0f);
            sx = nsx; cx = ncx; sy = nsy; cy = ncy; sz = nsz; cz = ncz;
        }
    }

    // -------- layer 4: relu(g) @ V2 + c2 -> rgb(3), sigmoid -------------
    float r0 = sc2[0], r1 = sc2[1], r2 = sc2[2];
#pragma unroll
    for (int jp = 0; jp < 32; jp++) {
        float g0, g1;
        upk(G[jp], g0, g1);
        g0 = fmaxf(g0, 0.0f);
        g1 = fmaxf(g1, 0.0f);
        const int j = 2 * jp;
        r0 = fmaf(g0, sV2[j * 3 + 0], r0);
        r1 = fmaf(g0, sV2[j * 3 + 1], r1);
        r2 = fmaf(g0, sV2[j * 3 + 2], r2);
        r0 = fmaf(g1, sV2[j * 3 + 3], r0);
        r1 = fmaf(g1, sV2[j * 3 + 4], r1);
        r2 = fmaf(g1, sV2[j * 3 + 5], r2);
    }
    r0 = 1.0f / (1.0f + __expf(-r0));
    r1 = 1.0f / (1.0f + __expf(-r1));
    r2 = 1.0f / (1.0f + __expf(-r2));

    g_scr[s * NR + ray] = make_float4(sigma, r0, r1, r2);
}

// ---------------------------------------------------------------------------
// Per-ray transmittance scan with reference early-stop semantics.
// ---------------------------------------------------------------------------
__global__ __launch_bounds__(256)
void scan_kernel(float* __restrict__ outp) {
    const int ray = blockIdx.x * 256 + threadIdx.x;
    if (ray >= NR) return;
    const float dt = g_dt;

    float T = 1.0f, r = 0.f, g = 0.f, b = 0.f;
#pragma unroll 4
    for (int s = 0; s < SS; s++) {
        const float4 v = g_scr[s * NR + ray];
        const float alpha = 1.0f - __expf(-v.x * dt);
        const bool active = T > 1e-4f;
        const float w = active ? T * alpha : 0.0f;
        r = fmaf(w, v.y, r);
        g = fmaf(w, v.z, g);
        b = fmaf(w, v.w, b);
        if (active) T *= (1.0f - alpha);
    }
    outp[ray * 3 + 0] = r;
    outp[ray * 3 + 1] = g;
    outp[ray * 3 + 2] = b;
    outp[3 * NR + ray] = T;
}

// ---------------------------------------------------------------------------
extern "C" void kernel_launch(void* const* d_in, const int* in_sizes, int n_in,
                              void* d_out, int out_size) {
    const float* orig = (const float*)d_in[0];
    const float* dirs = (const float*)d_in[1];
    const float* tmin = (const float*)d_in[2];
    const float* tmax = (const float*)d_in[3];
    const float* W1   = (const float*)d_in[4];
    const float* b1   = (const float*)d_in[5];
    const float* W2   = (const float*)d_in[6];
    const float* b2   = (const float*)d_in[7];
    const float* V1   = (const float*)d_in[8];
    const float* c1   = (const float*)d_in[9];
    const float* V2   = (const float*)d_in[10];
    const float* c2   = (const float*)d_in[11];

    dt_kernel<<<1, 1024>>>(tmin, tmax);
    mlp_kernel<<<(NR * SS) / 256, 256>>>(orig, dirs, tmin, tmax,
                                         W1, b1, W2, b2, V1, c1, V2, c2);
    scan_kernel<<<NR / 256, 256>>>((float*)d_out);
}

// round 3
// speedup vs baseline: 1.1914x; 1.0944x over previous
#include <cuda_runtime.h>
#include <math.h>

#define NR 8192      // rays
#define SS 128       // samples per ray
#define HID 64

typedef unsigned long long u64;

// Scratch / per-ray tables (static device arrays; no allocs allowed)
__device__ float4 g_scr[NR * SS];          // [ray][s] = (sigma, r, g, b)
__device__ float  g_base[NR * 64];         // c1 + V1 contribution of vd_enc (per ray)
__device__ float  g_P[NR * 64];            // b1 + W1[0..2] . orig
__device__ float  g_Q[NR * 64];            // W1[0..2] . dirs
__device__ float  g_dt;

// ---------------------------------------------------------------------------
// packed f32x2 helpers
// ---------------------------------------------------------------------------
__device__ __forceinline__ u64 pk(float a, float b) {
    u64 r; asm("mov.b64 %0,{%1,%2};" : "=l"(r) : "f"(a), "f"(b)); return r;
}
__device__ __forceinline__ void upk(u64 v, float& a, float& b) {
    asm("mov.b64 {%0,%1},%2;" : "=f"(a), "=f"(b) : "l"(v));
}
__device__ __forceinline__ u64 f2fma(u64 a, u64 b, u64 c) {
    u64 d; asm("fma.rn.f32x2 %0,%1,%2,%3;" : "=l"(d) : "l"(a), "l"(b), "l"(c)); return d;
}

// rank-1 accumulate, packed: H[0..31] (=64 floats) += vv * w[0..63]
__device__ __forceinline__ void acc64p(u64 (&H)[32], u64 vv, const float* __restrict__ w) {
#pragma unroll
    for (int k = 0; k < 16; k++) {
        const ulonglong2 wp = *reinterpret_cast<const ulonglong2*>(w + 4 * k);
        H[2 * k + 0] = f2fma(vv, wp.x, H[2 * k + 0]);
        H[2 * k + 1] = f2fma(vv, wp.y, H[2 * k + 1]);
    }
}

// ---------------------------------------------------------------------------
// dt = mean(tmax - tmin) / S
// ---------------------------------------------------------------------------
__global__ __launch_bounds__(1024)
void dt_kernel(const float* __restrict__ tmin, const float* __restrict__ tmax) {
    __shared__ float red[32];
    const int t = threadIdx.x;
    const float4* a = (const float4*)tmin;
    const float4* b = (const float4*)tmax;
    float s = 0.f;
#pragma unroll
    for (int i = t; i < NR / 4; i += 1024) {
        float4 x = a[i], y = b[i];
        s += (y.x - x.x) + (y.y - x.y) + (y.z - x.z) + (y.w - x.w);
    }
#pragma unroll
    for (int o = 16; o > 0; o >>= 1) s += __shfl_down_sync(0xffffffffu, s, o);
    if ((t & 31) == 0) red[t >> 5] = s;
    __syncthreads();
    if (t < 32) {
        float v = red[t];
#pragma unroll
        for (int o = 16; o > 0; o >>= 1) v += __shfl_down_sync(0xffffffffu, v, o);
        if (t == 0) g_dt = v / (float)(NR * SS);
    }
}

// ---------------------------------------------------------------------------
// Per-ray precompute: g_base (vd-enc through V1 + c1), g_P, g_Q.
// One thread per ray. 8192 threads total -> negligible runtime.
// ---------------------------------------------------------------------------
__global__ __launch_bounds__(128)
void ray_kernel(const float* __restrict__ orig, const float* __restrict__ dirs,
                const float* __restrict__ W1, const float* __restrict__ b1,
                const float* __restrict__ V1, const float* __restrict__ c1) {
    const int ray = blockIdx.x * 128 + threadIdx.x;
    if (ray >= NR) return;

    const float ox = orig[ray * 3 + 0], oy = orig[ray * 3 + 1], oz = orig[ray * 3 + 2];
    const float dx = dirs[ray * 3 + 0], dy = dirs[ray * 3 + 1], dz = dirs[ray * 3 + 2];

    const float nrm = sqrtf(dx * dx + dy * dy + dz * dz) + 1e-8f;
    const float inv = 1.0f / nrm;
    const float vx = dx * inv, vy = dy * inv, vz = dz * inv;

    // build the 27 vd-encoding scalars: [vx,vy,vz, (sin xyz, cos xyz) x 4 bands]
    float v[27];
    v[0] = vx; v[1] = vy; v[2] = vz;
    {
        float sx, cx, sy, cy, sz, cz;
        sincosf(vx, &sx, &cx);
        sincosf(vy, &sy, &cy);
        sincosf(vz, &sz, &cz);
#pragma unroll
        for (int i = 0; i < 4; i++) {
            v[3 + 6 * i + 0] = sx; v[3 + 6 * i + 1] = sy; v[3 + 6 * i + 2] = sz;
            v[3 + 6 * i + 3] = cx; v[3 + 6 * i + 4] = cy; v[3 + 6 * i + 5] = cz;
            const float nsx = 2.0f * sx * cx, ncx = fmaf(-2.0f * sx, sx, 1.0f);
            const float nsy = 2.0f * sy * cy, ncy = fmaf(-2.0f * sy, sy, 1.0f);
            const float nsz = 2.0f * sz * cz, ncz = fmaf(-2.0f * sz, sz, 1.0f);
            sx = nsx; cx = ncx; sy = nsy; cy = ncy; sz = nsz; cz = ncz;
        }
    }

    float acc[64];

    // g_base = c1 + sum_i v[i] * V1[15+i]
#pragma unroll
    for (int j = 0; j < 64; j++) acc[j] = c1[j];
#pragma unroll 1
    for (int i = 0; i < 27; i++) {
        const float vi = v[i];
        const float* w = V1 + (15 + i) * 64;
#pragma unroll
        for (int j = 0; j < 64; j++) acc[j] = fmaf(vi, w[j], acc[j]);
    }
#pragma unroll
    for (int j = 0; j < 64; j++) g_base[ray * 64 + j] = acc[j];

    // g_P = b1 + ox*W1[0] + oy*W1[1] + oz*W1[2]
#pragma unroll
    for (int j = 0; j < 64; j++)
        acc[j] = fmaf(ox, W1[0 * 64 + j], fmaf(oy, W1[1 * 64 + j], fmaf(oz, W1[2 * 64 + j], b1[j])));
#pragma unroll
    for (int j = 0; j < 64; j++) g_P[ray * 64 + j] = acc[j];

    // g_Q = dx*W1[0] + dy*W1[1] + dz*W1[2]
#pragma unroll
    for (int j = 0; j < 64; j++)
        acc[j] = fmaf(dx, W1[0 * 64 + j], fmaf(dy, W1[1 * 64 + j], dz * W1[2 * 64 + j]));
#pragma unroll
    for (int j = 0; j < 64; j++) g_Q[ray * 64 + j] = acc[j];
}

// ---------------------------------------------------------------------------
// Per-sample MLP kernel: ray-major order (warp = 32 samples of one ray).
// gid = ray*SS + s  -> per-ray loads are warp-uniform broadcasts.
// ---------------------------------------------------------------------------
__global__ __launch_bounds__(256)
void mlp_kernel(const float* __restrict__ orig, const float* __restrict__ dirs,
                const float* __restrict__ tmin, const float* __restrict__ tmax,
                const float* __restrict__ W1,
                const float* __restrict__ W2, const float* __restrict__ b2,
                const float* __restrict__ V1,
                const float* __restrict__ V2, const float* __restrict__ c2) {
    // sW1 holds rows 3..62 of W1 (the 10 sin/cos bands); sV1 rows 0..14 (rgb feats)
    __shared__ __align__(16) float sW1[60 * 64];
    __shared__ __align__(16) float sW2[64 * 16];
    __shared__ __align__(16) float sb2[16];
    __shared__ __align__(16) float sV1[15 * 64];
    __shared__ __align__(16) float sV2[64 * 3];
    __shared__ __align__(16) float sc2[4];

    const int t = threadIdx.x;
    for (int i = t; i < 60 * 64; i += 256) sW1[i] = W1[3 * 64 + i];
    for (int i = t; i < 64 * 16; i += 256) sW2[i] = W2[i];
    for (int i = t; i < 16; i += 256)      sb2[i] = b2[i];
    for (int i = t; i < 15 * 64; i += 256) sV1[i] = V1[i];
    for (int i = t; i < 64 * 3; i += 256)  sV2[i] = V2[i];
    if (t < 3) sc2[t] = c2[t];
    __syncthreads();

    const int gid = blockIdx.x * 256 + t;
    const int ray = gid >> 7;        // SS = 128
    const int s   = gid & (SS - 1);

    const float t0 = tmin[ray], t1 = tmax[ray];
    const float tu = (float)s * (1.0f / (SS - 1));
    const float tt = t0 + tu * (t1 - t0);

    // -------- MLP 1 init: H = P + t * Q  (warp-uniform loads) -----------
    u64 H[32];
    {
        const float4* P4 = (const float4*)(g_P + ray * 64);
        const float4* Q4 = (const float4*)(g_Q + ray * 64);
        const u64 tp = pk(tt, tt);
#pragma unroll
        for (int k = 0; k < 16; k++) {
            const float4 p = P4[k];
            const float4 q = Q4[k];
            H[2 * k + 0] = f2fma(tp, pk(q.x, q.y), pk(p.x, p.y));
            H[2 * k + 1] = f2fma(tp, pk(q.z, q.w), pk(p.z, p.w));
        }
    }

    const float dx = dirs[ray * 3 + 0], dy = dirs[ray * 3 + 1], dz = dirs[ray * 3 + 2];
    const float px = fmaf(dx, tt, orig[ray * 3 + 0]);
    const float py = fmaf(dy, tt, orig[ray * 3 + 1]);
    const float pz = fmaf(dz, tt, orig[ray * 3 + 2]);

    // -------- positional sin/cos bands via double-angle ladder ----------
    {
        float sx, cx, sy, cy, sz, cz;
        sincosf(px, &sx, &cx);
        sincosf(py, &sy, &cy);
        sincosf(pz, &sz, &cz);
#pragma unroll 1
        for (int i = 0; i < 10; i++) {
            const float* base = sW1 + (6 * i) * 64;
            acc64p(H, pk(sx, sx), base + 0 * 64);
            acc64p(H, pk(sy, sy), base + 1 * 64);
            acc64p(H, pk(sz, sz), base + 2 * 64);
            acc64p(H, pk(cx, cx), base + 3 * 64);
            acc64p(H, pk(cy, cy), base + 4 * 64);
            acc64p(H, pk(cz, cz), base + 5 * 64);
            const float nsx = 2.0f * sx * cx, ncx = fmaf(-2.0f * sx, sx, 1.0f);
            const float nsy = 2.0f * sy * cy, ncy = fmaf(-2.0f * sy, sy, 1.0f);
            const float nsz = 2.0f * sz * cz, ncz = fmaf(-2.0f * sz, sz, 1.0f);
            sx = nsx; cx = ncx; sy = nsy; cy = ncy; sz = nsz; cz = ncz;
        }
    }

    // -------- layer 2: relu(h) @ W2 + b2 -> out(16), packed -------------
    u64 O[8];
#pragma unroll
    for (int k = 0; k < 4; k++) {
        const ulonglong2 bp = *reinterpret_cast<const ulonglong2*>(sb2 + 4 * k);
        O[2 * k + 0] = bp.x;
        O[2 * k + 1] = bp.y;
    }
#pragma unroll
    for (int jp = 0; jp < 32; jp++) {
        float h0, h1;
        upk(H[jp], h0, h1);
        h0 = fmaxf(h0, 0.0f);
        h1 = fmaxf(h1, 0.0f);
        const u64 v0 = pk(h0, h0), v1 = pk(h1, h1);
        const float* r0w = sW2 + (2 * jp + 0) * 16;
        const float* r1w = sW2 + (2 * jp + 1) * 16;
#pragma unroll
        for (int m = 0; m < 4; m++) {
            const ulonglong2 w0 = *reinterpret_cast<const ulonglong2*>(r0w + 4 * m);
            const ulonglong2 w1 = *reinterpret_cast<const ulonglong2*>(r1w + 4 * m);
            O[2 * m + 0] = f2fma(v0, w0.x, O[2 * m + 0]);
            O[2 * m + 1] = f2fma(v0, w0.y, O[2 * m + 1]);
            O[2 * m + 0] = f2fma(v1, w1.x, O[2 * m + 0]);
            O[2 * m + 1] = f2fma(v1, w1.y, O[2 * m + 1]);
        }
    }

    float out[16];
#pragma unroll
    for (int k = 0; k < 8; k++) upk(O[k], out[2 * k], out[2 * k + 1]);

    const float sigma = fmaxf(out[0], 0.0f);

    // -------- MLP 2: G = g_base + sum feats (vd part precomputed) -------
    u64 G[32];
    {
        const float4* B4 = (const float4*)(g_base + ray * 64);
#pragma unroll
        for (int k = 0; k < 16; k++) {
            const float4 b = B4[k];
            G[2 * k + 0] = pk(b.x, b.y);
            G[2 * k + 1] = pk(b.z, b.w);
        }
    }
#pragma unroll
    for (int f = 0; f < 15; f++) acc64p(G, pk(out[1 + f], out[1 + f]), sV1 + f * 64);

    // -------- layer 4: relu(g) @ V2 + c2 -> rgb(3), sigmoid -------------
    float r0 = sc2[0], r1 = sc2[1], r2 = sc2[2];
#pragma unroll
    for (int jp = 0; jp < 32; jp++) {
        float g0, g1;
        upk(G[jp], g0, g1);
        g0 = fmaxf(g0, 0.0f);
        g1 = fmaxf(g1, 0.0f);
        const int j = 2 * jp;
        r0 = fmaf(g0, sV2[j * 3 + 0], r0);
        r1 = fmaf(g0, sV2[j * 3 + 1], r1);
        r2 = fmaf(g0, sV2[j * 3 + 2], r2);
        r0 = fmaf(g1, sV2[j * 3 + 3], r0);
        r1 = fmaf(g1, sV2[j * 3 + 4], r1);
        r2 = fmaf(g1, sV2[j * 3 + 5], r2);
    }
    r0 = 1.0f / (1.0f + __expf(-r0));
    r1 = 1.0f / (1.0f + __expf(-r1));
    r2 = 1.0f / (1.0f + __expf(-r2));

    g_scr[ray * SS + s] = make_float4(sigma, r0, r1, r2);
}

// ---------------------------------------------------------------------------
// Per-ray transmittance scan (reference early-stop semantics).
// Scratch now [ray][s].
// ---------------------------------------------------------------------------
__global__ __launch_bounds__(256)
void scan_kernel(float* __restrict__ outp) {
    const int ray = blockIdx.x * 256 + threadIdx.x;
    if (ray >= NR) return;
    const float dt = g_dt;
    const float4* row = g_scr + ray * SS;

    float T = 1.0f, r = 0.f, g = 0.f, b = 0.f;
#pragma unroll 4
    for (int s = 0; s < SS; s++) {
        const float4 v = row[s];
        const float alpha = 1.0f - __expf(-v.x * dt);
        const bool active = T > 1e-4f;
        const float w = active ? T * alpha : 0.0f;
        r = fmaf(w, v.y, r);
        g = fmaf(w, v.z, g);
        b = fmaf(w, v.w, b);
        if (active) T *= (1.0f - alpha);
    }
    outp[ray * 3 + 0] = r;
    outp[ray * 3 + 1] = g;
    outp[ray * 3 + 2] = b;
    outp[3 * NR + ray] = T;
}

// ---------------------------------------------------------------------------
extern "C" void kernel_launch(void* const* d_in, const int* in_sizes, int n_in,
                              void* d_out, int out_size) {
    const float* orig = (const float*)d_in[0];
    const float* dirs = (const float*)d_in[1];
    const float* tmin = (const float*)d_in[2];
    const float* tmax = (const float*)d_in[3];
    const float* W1   = (const float*)d_in[4];
    const float* b1   = (const float*)d_in[5];
    const float* W2   = (const float*)d_in[6];
    const float* b2   = (const float*)d_in[7];
    const float* V1   = (const float*)d_in[8];
    const float* c1   = (const float*)d_in[9];
    const float* V2   = (const float*)d_in[10];
    const float* c2   = (const float*)d_in[11];

    dt_kernel<<<1, 1024>>>(tmin, tmax);
    ray_kernel<<<NR / 128, 128>>>(orig, dirs, W1, b1, V1, c1);
    mlp_kernel<<<(NR * SS) / 256, 256>>>(orig, dirs, tmin, tmax,
                                         W1, W2, b2, V1, V2, c2);
    scan_kernel<<<NR / 256, 256>>>((float*)d_out);
}

// round 7
// speedup vs baseline: 2.1136x; 1.7740x over previous
#include <cuda_runtime.h>
#include <cuda_bf16.h>
#include <math.h>

#define NR 8192
#define SS 128
#define GRIDF 296
#define THREADS 256

typedef unsigned int u32;

__device__ float g_base_arr[NR * 64];   // c1 + vd_enc @ V1[15:42]  (per ray)
__device__ float g_dt;

// ---------------- smem layout (bytes) ----------------
#define OFF_AH   0                 // 8 warps x 32 rows x 144B (bf16 hi)
#define OFF_AL   36864             // lo plane
#define OFF_W1H  73728             // W1^T [64n][72 bf16 stride], K pad 64
#define OFF_W1L  82944
#define OFF_W2H  92160             // W2^T [16n][72]
#define OFF_W2L  94464
#define OFF_B3H  96768             // V1[0:15]^T shifted: [64n][20 bf16 stride], k0=0
#define OFF_B3L  99328
#define OFF_B4H  101888            // V2^T [8n][72], n>=3 zero
#define OFF_B4L  103040
#define OFF_B1   104192            // b1 (64 f32)
#define OFF_B2   104448            // b2 (16 f32)
#define OFF_C2   104512            // c2 (8 f32, padded)
#define OFF_RED  104544            // 2 rays x 4 warp products
#define OFF_PART 104576            // 2 rays x 4 warps x 4 floats
#define SMEM_TOTAL 104704

static __device__ __forceinline__ u32 pk2(__nv_bfloat16 a, __nv_bfloat16 b) {
    return (u32)__bfloat16_as_ushort(a) | ((u32)__bfloat16_as_ushort(b) << 16);
}
static __device__ __forceinline__ void split2(float x, float y, u32& hi, u32& lo) {
    __nv_bfloat16 hx = __float2bfloat16(x), hy = __float2bfloat16(y);
    hi = pk2(hx, hy);
    lo = pk2(__float2bfloat16(x - __bfloat162float(hx)),
             __float2bfloat16(y - __bfloat162float(hy)));
}
static __device__ __forceinline__ void mma4(float* d, const u32* a, u32 b0, u32 b1) {
    asm volatile(
        "mma.sync.aligned.m16n8k16.row.col.f32.bf16.bf16.f32 "
        "{%0,%1,%2,%3}, {%4,%5,%6,%7}, {%8,%9}, {%0,%1,%2,%3};"
        : "+f"(d[0]), "+f"(d[1]), "+f"(d[2]), "+f"(d[3])
        : "r"(a[0]), "r"(a[1]), "r"(a[2]), "r"(a[3]), "r"(b0), "r"(b1));
}

// ---------------------------------------------------------------------------
// dt = mean(tmax - tmin) / S
// ---------------------------------------------------------------------------
__global__ __launch_bounds__(1024)
void dt_kernel(const float* __restrict__ tmin, const float* __restrict__ tmax) {
    __shared__ float red[32];
    const int t = threadIdx.x;
    const float4* a = (const float4*)tmin;
    const float4* b = (const float4*)tmax;
    float s = 0.f;
    for (int i = t; i < NR / 4; i += 1024) {
        float4 x = a[i], y = b[i];
        s += (y.x - x.x) + (y.y - x.y) + (y.z - x.z) + (y.w - x.w);
    }
#pragma unroll
    for (int o = 16; o > 0; o >>= 1) s += __shfl_down_sync(0xffffffffu, s, o);
    if ((t & 31) == 0) red[t >> 5] = s;
    __syncthreads();
    if (t < 32) {
        float v = red[t];
#pragma unroll
        for (int o = 16; o > 0; o >>= 1) v += __shfl_down_sync(0xffffffffu, v, o);
        if (t == 0) g_dt = v / (float)(NR * SS);
    }
}

// ---------------------------------------------------------------------------
// Per-ray: g_base = c1 + vd_enc @ V1[15:42]
// ---------------------------------------------------------------------------
__global__ __launch_bounds__(128)
void ray_kernel(const float* __restrict__ dirs,
                const float* __restrict__ V1, const float* __restrict__ c1) {
    const int ray = blockIdx.x * 128 + threadIdx.x;
    if (ray >= NR) return;
    const float dx = dirs[ray * 3 + 0], dy = dirs[ray * 3 + 1], dz = dirs[ray * 3 + 2];
    const float nrm = sqrtf(dx * dx + dy * dy + dz * dz) + 1e-8f;
    const float inv = 1.0f / nrm;
    const float vx = dx * inv, vy = dy * inv, vz = dz * inv;

    float v[27];
    v[0] = vx; v[1] = vy; v[2] = vz;
    {
        float sx, cx, sy, cy, sz, cz;
        sincosf(vx, &sx, &cx); sincosf(vy, &sy, &cy); sincosf(vz, &sz, &cz);
#pragma unroll
        for (int i = 0; i < 4; i++) {
            v[3 + 6 * i + 0] = sx; v[3 + 6 * i + 1] = sy; v[3 + 6 * i + 2] = sz;
            v[3 + 6 * i + 3] = cx; v[3 + 6 * i + 4] = cy; v[3 + 6 * i + 5] = cz;
            const float nsx = 2.f * sx * cx, ncx = fmaf(-2.f * sx, sx, 1.f);
            const float nsy = 2.f * sy * cy, ncy = fmaf(-2.f * sy, sy, 1.f);
            const float nsz = 2.f * sz * cz, ncz = fmaf(-2.f * sz, sz, 1.f);
            sx = nsx; cx = ncx; sy = nsy; cy = ncy; sz = nsz; cz = ncz;
        }
    }
    float acc[64];
#pragma unroll
    for (int j = 0; j < 64; j++) acc[j] = c1[j];
#pragma unroll 1
    for (int i = 0; i < 27; i++) {
        const float vi = v[i];
        const float* w = V1 + (15 + i) * 64;
#pragma unroll
        for (int j = 0; j < 64; j++) acc[j] = fmaf(vi, w[j], acc[j]);
    }
#pragma unroll
    for (int j = 0; j < 64; j++) g_base_arr[ray * 64 + j] = acc[j];
}

// ---------------------------------------------------------------------------
// Fused ray-marcher: 256 threads = 8 warps = 2 rays per iteration.
// Warp w handles samples (w%4)*32 .. +31 of ray rbase + w/4.
// ---------------------------------------------------------------------------
__global__ __launch_bounds__(THREADS, 1)
void fused_kernel(const float* __restrict__ orig, const float* __restrict__ dirs,
                  const float* __restrict__ tmin, const float* __restrict__ tmax,
                  const float* __restrict__ W1, const float* __restrict__ b1,
                  const float* __restrict__ W2, const float* __restrict__ b2,
                  const float* __restrict__ V1, const float* __restrict__ V2,
                  const float* __restrict__ c2, float* __restrict__ outp) {
    extern __shared__ char dsm[];
    const int tid = threadIdx.x;
    const int w = tid >> 5, lane = tid & 31, g = lane >> 2, tig = lane & 3;

    // ---------------- stage weights: split bf16 hi/lo, K-major padded ------
    for (int i = tid; i < 64 * 64; i += THREADS) {            // W1^T, K pad 64
        int n = i >> 6, k = i & 63;
        float v = (k < 63) ? W1[k * 64 + n] : 0.f;
        __nv_bfloat16 h = __float2bfloat16(v);
        *(__nv_bfloat16*)(dsm + OFF_W1H + n * 144 + k * 2) = h;
        *(__nv_bfloat16*)(dsm + OFF_W1L + n * 144 + k * 2) =
            __float2bfloat16(v - __bfloat162float(h));
    }
    for (int i = tid; i < 16 * 64; i += THREADS) {            // W2^T
        int n = i >> 6, k = i & 63;
        float v = W2[k * 16 + n];
        __nv_bfloat16 h = __float2bfloat16(v);
        *(__nv_bfloat16*)(dsm + OFF_W2H + n * 144 + k * 2) = h;
        *(__nv_bfloat16*)(dsm + OFF_W2L + n * 144 + k * 2) =
            __float2bfloat16(v - __bfloat162float(h));
    }
    for (int i = tid; i < 64 * 16; i += THREADS) {            // B3 = shifted V1[0:15]^T
        int n = i >> 4, k = i & 15;
        float v = (k >= 1) ? V1[(k - 1) * 64 + n] : 0.f;
        __nv_bfloat16 h = __float2bfloat16(v);
        *(__nv_bfloat16*)(dsm + OFF_B3H + n * 40 + k * 2) = h;
        *(__nv_bfloat16*)(dsm + OFF_B3L + n * 40 + k * 2) =
            __float2bfloat16(v - __bfloat162float(h));
    }
    for (int i = tid; i < 8 * 64; i += THREADS) {             // B4 = V2^T, n pad 8
        int n = i >> 6, k = i & 63;
        float v = (n < 3) ? V2[k * 3 + n] : 0.f;
        __nv_bfloat16 h = __float2bfloat16(v);
        *(__nv_bfloat16*)(dsm + OFF_B4H + n * 144 + k * 2) = h;
        *(__nv_bfloat16*)(dsm + OFF_B4L + n * 144 + k * 2) =
            __float2bfloat16(v - __bfloat162float(h));
    }
    for (int i = tid; i < 64; i += THREADS) ((float*)(dsm + OFF_B1))[i] = b1[i];
    if (tid < 16) ((float*)(dsm + OFF_B2))[tid] = b2[tid];
    if (tid < 8)  ((float*)(dsm + OFF_C2))[tid] = (tid < 3) ? c2[tid] : 0.f;
    __syncthreads();

    const float dtv = g_dt;
    const u32 FULL = 0xffffffffu;

    for (int rbase = blockIdx.x * 2; rbase < NR; rbase += 2 * GRIDF) {
        const int ray = rbase + (w >> 2);
        const int rs  = w >> 2;
        const int s   = ((w & 3) << 5) + lane;

        // ---------------- positional encoding, row = lane -------------------
        const float dx = dirs[ray * 3 + 0], dy = dirs[ray * 3 + 1], dz = dirs[ray * 3 + 2];
        const float t0 = tmin[ray], t1 = tmax[ray];
        const float tt = t0 + (float)s * (1.0f / (SS - 1)) * (t1 - t0);
        float enc[64];
        enc[0] = fmaf(dx, tt, orig[ray * 3 + 0]);
        enc[1] = fmaf(dy, tt, orig[ray * 3 + 1]);
        enc[2] = fmaf(dz, tt, orig[ray * 3 + 2]);
        {
            float sx, cx, sy, cy, sz, cz;
            sincosf(enc[0], &sx, &cx); sincosf(enc[1], &sy, &cy); sincosf(enc[2], &sz, &cz);
#pragma unroll
            for (int i = 0; i < 10; i++) {
                enc[3 + 6 * i + 0] = sx; enc[3 + 6 * i + 1] = sy; enc[3 + 6 * i + 2] = sz;
                enc[3 + 6 * i + 3] = cx; enc[3 + 6 * i + 4] = cy; enc[3 + 6 * i + 5] = cz;
                const float nsx = 2.f * sx * cx, ncx = fmaf(-2.f * sx, sx, 1.f);
                const float nsy = 2.f * sy * cy, ncy = fmaf(-2.f * sy, sy, 1.f);
                const float nsz = 2.f * sz * cz, ncz = fmaf(-2.f * sz, sz, 1.f);
                sx = nsx; cx = ncx; sy = nsy; cy = ncy; sz = nsz; cz = ncz;
            }
        }
        enc[63] = 0.f;
        {
            char* Ah = dsm + OFF_AH + w * 4608 + lane * 144;
            char* Al = dsm + OFF_AL + w * 4608 + lane * 144;
#pragma unroll
            for (int j8 = 0; j8 < 8; j8++) {
                u32 h0, l0, h1, l1, h2, l2, h3, l3;
                split2(enc[8 * j8 + 0], enc[8 * j8 + 1], h0, l0);
                split2(enc[8 * j8 + 2], enc[8 * j8 + 3], h1, l1);
                split2(enc[8 * j8 + 4], enc[8 * j8 + 5], h2, l2);
                split2(enc[8 * j8 + 6], enc[8 * j8 + 7], h3, l3);
                *(uint4*)(Ah + j8 * 16) = make_uint4(h0, h1, h2, h3);
                *(uint4*)(Al + j8 * 16) = make_uint4(l0, l1, l2, l3);
            }
        }
        __syncwarp();

        // ---------------- MLP1: enc(64) @ W1 -> 32x64 -----------------------
        float acc[2][8][4];
#pragma unroll
        for (int mt = 0; mt < 2; mt++)
#pragma unroll
            for (int nt = 0; nt < 8; nt++)
#pragma unroll
                for (int r = 0; r < 4; r++) acc[mt][nt][r] = 0.f;

        const char* AHb = dsm + OFF_AH + w * 4608;
        const char* ALb = dsm + OFF_AL + w * 4608;
#pragma unroll
        for (int kt = 0; kt < 4; kt++) {
            u32 AH[2][4], AL[2][4];
#pragma unroll
            for (int mt = 0; mt < 2; mt++) {
                int ab = mt * 2304 + g * 144 + kt * 32 + tig * 4;
                AH[mt][0] = *(const u32*)(AHb + ab);
                AH[mt][1] = *(const u32*)(AHb + ab + 1152);
                AH[mt][2] = *(const u32*)(AHb + ab + 16);      // k-cols +8 = +16B
                AH[mt][3] = *(const u32*)(AHb + ab + 1168);
                AL[mt][0] = *(const u32*)(ALb + ab);
                AL[mt][1] = *(const u32*)(ALb + ab + 1152);
                AL[mt][2] = *(const u32*)(ALb + ab + 16);
                AL[mt][3] = *(const u32*)(ALb + ab + 1168);
            }
#pragma unroll
            for (int nt = 0; nt < 8; nt++) {
                int bo = (nt * 8 + g) * 144 + kt * 32 + tig * 4;
                u32 bh0 = *(const u32*)(dsm + OFF_W1H + bo);
                u32 bh1 = *(const u32*)(dsm + OFF_W1H + bo + 16);
                u32 bl0 = *(const u32*)(dsm + OFF_W1L + bo);
                u32 bl1 = *(const u32*)(dsm + OFF_W1L + bo + 16);
#pragma unroll
                for (int mt = 0; mt < 2; mt++) {
                    mma4(acc[mt][nt], AH[mt], bh0, bh1);
                    mma4(acc[mt][nt], AH[mt], bl0, bl1);
                    mma4(acc[mt][nt], AL[mt], bh0, bh1);
                }
            }
        }

        // ---------------- epi1: h = relu(D + b1) -> A frags (regs) ----------
        u32 HF[2][4][4], HL[2][4][4];
#pragma unroll
        for (int kt = 0; kt < 4; kt++)
#pragma unroll
            for (int j = 0; j < 2; j++) {
                const int nt = 2 * kt + j;
                const float2 bb = *(const float2*)(dsm + OFF_B1 + (nt * 8 + tig * 2) * 4);
#pragma unroll
                for (int mt = 0; mt < 2; mt++) {
                    float v0 = fmaxf(acc[mt][nt][0] + bb.x, 0.f);
                    float v1 = fmaxf(acc[mt][nt][1] + bb.y, 0.f);
                    float v2 = fmaxf(acc[mt][nt][2] + bb.x, 0.f);
                    float v3 = fmaxf(acc[mt][nt][3] + bb.y, 0.f);
                    split2(v0, v1, HF[mt][kt][2 * j + 0], HL[mt][kt][2 * j + 0]);
                    split2(v2, v3, HF[mt][kt][2 * j + 1], HL[mt][kt][2 * j + 1]);
                }
            }

        // ---------------- MLP2: h @ W2 -> 32x16 -----------------------------
        float a2c[2][2][4];
#pragma unroll
        for (int mt = 0; mt < 2; mt++)
#pragma unroll
            for (int n2 = 0; n2 < 2; n2++)
#pragma unroll
                for (int r = 0; r < 4; r++) a2c[mt][n2][r] = 0.f;
#pragma unroll
        for (int kt = 0; kt < 4; kt++)
#pragma unroll
            for (int n2 = 0; n2 < 2; n2++) {
                int bo = (n2 * 8 + g) * 144 + kt * 32 + tig * 4;
                u32 bh0 = *(const u32*)(dsm + OFF_W2H + bo);
                u32 bh1 = *(const u32*)(dsm + OFF_W2H + bo + 16);
                u32 bl0 = *(const u32*)(dsm + OFF_W2L + bo);
                u32 bl1 = *(const u32*)(dsm + OFF_W2L + bo + 16);
#pragma unroll
                for (int mt = 0; mt < 2; mt++) {
                    mma4(a2c[mt][n2], HF[mt][kt], bh0, bh1);
                    mma4(a2c[mt][n2], HF[mt][kt], bl0, bl1);
                    mma4(a2c[mt][n2], HL[mt][kt], bh0, bh1);
                }
            }

        // ---------------- epi2: sigma raw + feat frags ----------------------
        float sgm[2][2];
        u32 FF[2][4], FL[2][4];
        {
            const float2 b20 = *(const float2*)(dsm + OFF_B2 + tig * 8);
            const float2 b21 = *(const float2*)(dsm + OFF_B2 + 32 + tig * 8);
#pragma unroll
            for (int mt = 0; mt < 2; mt++) {
                float v0 = a2c[mt][0][0] + b20.x;
                float v1 = a2c[mt][0][1] + b20.y;
                float v2 = a2c[mt][0][2] + b20.x;
                float v3 = a2c[mt][0][3] + b20.y;
                float u0 = a2c[mt][1][0] + b21.x;
                float u1 = a2c[mt][1][1] + b21.y;
                float u2 = a2c[mt][1][2] + b21.x;
                float u3 = a2c[mt][1][3] + b21.y;
                sgm[mt][0] = v0;
                sgm[mt][1] = v2;
                split2(v0, v1, FF[mt][0], FL[mt][0]);
                split2(v2, v3, FF[mt][1], FL[mt][1]);
                split2(u0, u1, FF[mt][2], FL[mt][2]);
                split2(u2, u3, FF[mt][3], FL[mt][3]);
            }
        }

        // ---------------- MLP3: feats(16) @ B3 -> 32x64 ---------------------
        float a3c[2][8][4];
#pragma unroll
        for (int mt = 0; mt < 2; mt++)
#pragma unroll
            for (int nt = 0; nt < 8; nt++)
#pragma unroll
                for (int r = 0; r < 4; r++) a3c[mt][nt][r] = 0.f;
#pragma unroll
        for (int nt = 0; nt < 8; nt++) {
            int bo = (nt * 8 + g) * 40 + tig * 4;
            u32 bh0 = *(const u32*)(dsm + OFF_B3H + bo);
            u32 bh1 = *(const u32*)(dsm + OFF_B3H + bo + 16);
            u32 bl0 = *(const u32*)(dsm + OFF_B3L + bo);
            u32 bl1 = *(const u32*)(dsm + OFF_B3L + bo + 16);
#pragma unroll
            for (int mt = 0; mt < 2; mt++) {
                mma4(a3c[mt][nt], FF[mt], bh0, bh1);
                mma4(a3c[mt][nt], FF[mt], bl0, bl1);
                mma4(a3c[mt][nt], FL[mt], bh0, bh1);
            }
        }

        // ---------------- epi3: g = relu(D + g_base) -> g frags -------------
        u32 GF[2][4][4], GL[2][4][4];
        const float* gb = g_base_arr + ray * 64;
#pragma unroll
        for (int kt = 0; kt < 4; kt++)
#pragma unroll
            for (int j = 0; j < 2; j++) {
                const int nt = 2 * kt + j;
                const float2 gv = __ldg((const float2*)(gb + nt * 8 + tig * 2));
#pragma unroll
                for (int mt = 0; mt < 2; mt++) {
                    float v0 = fmaxf(a3c[mt][nt][0] + gv.x, 0.f);
                    float v1 = fmaxf(a3c[mt][nt][1] + gv.y, 0.f);
                    float v2 = fmaxf(a3c[mt][nt][2] + gv.x, 0.f);
                    float v3 = fmaxf(a3c[mt][nt][3] + gv.y, 0.f);
                    split2(v0, v1, GF[mt][kt][2 * j + 0], GL[mt][kt][2 * j + 0]);
                    split2(v2, v3, GF[mt][kt][2 * j + 1], GL[mt][kt][2 * j + 1]);
                }
            }

        // ---------------- MLP4: g @ V2 -> 32x8 ------------------------------
        float a4[2][4];
#pragma unroll
        for (int mt = 0; mt < 2; mt++)
#pragma unroll
            for (int r = 0; r < 4; r++) a4[mt][r] = 0.f;
#pragma unroll
        for (int kt = 0; kt < 4; kt++) {
            int bo = g * 144 + kt * 32 + tig * 4;
            u32 bh0 = *(const u32*)(dsm + OFF_B4H + bo);
            u32 bh1 = *(const u32*)(dsm + OFF_B4H + bo + 16);
            u32 bl0 = *(const u32*)(dsm + OFF_B4L + bo);
            u32 bl1 = *(const u32*)(dsm + OFF_B4L + bo + 16);
#pragma unroll
            for (int mt = 0; mt < 2; mt++) {
                mma4(a4[mt], GF[mt][kt], bh0, bh1);
                mma4(a4[mt], GF[mt][kt], bl0, bl1);
                mma4(a4[mt], GL[mt][kt], bh0, bh1);
            }
        }

        // ---------------- epi4 + redistribution lane<->row ------------------
        float o0[2], o1[2], o2[2], o3[2];
        {
            const float2 cc = *(const float2*)(dsm + OFF_C2 + tig * 8);
#pragma unroll
            for (int mt = 0; mt < 2; mt++) {
                o0[mt] = a4[mt][0] + cc.x;
                o1[mt] = a4[mt][1] + cc.y;
                o2[mt] = a4[mt][2] + cc.x;
                o3[mt] = a4[mt][3] + cc.y;
            }
        }
        const int q4 = (lane & 7) * 4;
        const int selv = lane >> 3;
        float x0, x1, x2, x3;
        x0 = __shfl_sync(FULL, sgm[0][0], q4);
        x1 = __shfl_sync(FULL, sgm[0][1], q4);
        x2 = __shfl_sync(FULL, sgm[1][0], q4);
        x3 = __shfl_sync(FULL, sgm[1][1], q4);
        const float sigma = fmaxf(selv == 0 ? x0 : selv == 1 ? x1 : selv == 2 ? x2 : x3, 0.f);
        x0 = __shfl_sync(FULL, o0[0], q4);
        x1 = __shfl_sync(FULL, o2[0], q4);
        x2 = __shfl_sync(FULL, o0[1], q4);
        x3 = __shfl_sync(FULL, o2[1], q4);
        const float rv = selv == 0 ? x0 : selv == 1 ? x1 : selv == 2 ? x2 : x3;
        x0 = __shfl_sync(FULL, o1[0], q4);
        x1 = __shfl_sync(FULL, o3[0], q4);
        x2 = __shfl_sync(FULL, o1[1], q4);
        x3 = __shfl_sync(FULL, o3[1], q4);
        const float gvv = selv == 0 ? x0 : selv == 1 ? x1 : selv == 2 ? x2 : x3;
        x0 = __shfl_sync(FULL, o0[0], q4 + 1);
        x1 = __shfl_sync(FULL, o2[0], q4 + 1);
        x2 = __shfl_sync(FULL, o0[1], q4 + 1);
        x3 = __shfl_sync(FULL, o2[1], q4 + 1);
        const float bv = selv == 0 ? x0 : selv == 1 ? x1 : selv == 2 ? x2 : x3;
        const float rr = 1.f / (1.f + __expf(-rv));
        const float rg = 1.f / (1.f + __expf(-gvv));
        const float rb = 1.f / (1.f + __expf(-bv));

        // ---------------- transmittance scan --------------------------------
        {
            const float ex = __expf(-sigma * dtv);      // one_minus
            const float alpha = 1.f - ex;
            float p = ex;
#pragma unroll
            for (int o = 1; o < 32; o <<= 1) {
                float q = __shfl_up_sync(FULL, p, o);
                if (lane >= o) p *= q;
            }
            float* red = (float*)(dsm + OFF_RED) + rs * 4;
            if (lane == 31) red[w & 3] = p;
            __syncthreads();
            float wpre = 1.f;
#pragma unroll
            for (int k = 0; k < 3; k++)
                if (k < (w & 3)) wpre *= red[k];
            const float pm1 = __shfl_up_sync(FULL, p, 1);
            const float excl = (lane == 0) ? wpre : wpre * pm1;
            const bool active = excl > 1e-4f;
            const float wgt = active ? excl * alpha : 0.f;
            float sr = wgt * rr, sg2 = wgt * rg, sb = wgt * rb;
            float ft = active ? ex : 1.f;
#pragma unroll
            for (int o = 16; o > 0; o >>= 1) {
                sr += __shfl_xor_sync(FULL, sr, o);
                sg2 += __shfl_xor_sync(FULL, sg2, o);
                sb += __shfl_xor_sync(FULL, sb, o);
                ft *= __shfl_xor_sync(FULL, ft, o);
            }
            float* part = (float*)(dsm + OFF_PART) + rs * 16 + (w & 3) * 4;
            if (lane == 0) { part[0] = sr; part[1] = sg2; part[2] = sb; part[3] = ft; }
            __syncthreads();
            if ((w & 3) == 0 && lane == 0) {
                const float* pp = (const float*)(dsm + OFF_PART) + rs * 16;
                float R = 0, G = 0, B = 0, T = 1.f;
#pragma unroll
                for (int k = 0; k < 4; k++) {
                    R += pp[k * 4 + 0]; G += pp[k * 4 + 1];
                    B += pp[k * 4 + 2]; T *= pp[k * 4 + 3];
                }
                outp[ray * 3 + 0] = R;
                outp[ray * 3 + 1] = G;
                outp[ray * 3 + 2] = B;
                outp[3 * NR + ray] = T;
            }
            __syncthreads();
        }
    }
}

// ---------------------------------------------------------------------------
extern "C" void kernel_launch(void* const* d_in, const int* in_sizes, int n_in,
                              void* d_out, int out_size) {
    const float* orig = (const float*)d_in[0];
    const float* dirs = (const float*)d_in[1];
    const float* tmin = (const float*)d_in[2];
    const float* tmax = (const float*)d_in[3];
    const float* W1   = (const float*)d_in[4];
    const float* b1   = (const float*)d_in[5];
    const float* W2   = (const float*)d_in[6];
    const float* b2   = (const float*)d_in[7];
    const float* V1   = (const float*)d_in[8];
    const float* c1   = (const float*)d_in[9];
    const float* V2   = (const float*)d_in[10];
    const float* c2   = (const float*)d_in[11];

    cudaFuncSetAttribute(fused_kernel, cudaFuncAttributeMaxDynamicSharedMemorySize, SMEM_TOTAL);

    dt_kernel<<<1, 1024>>>(tmin, tmax);
    ray_kernel<<<NR / 128, 128>>>(dirs, V1, c1);
    fused_kernel<<<GRIDF, THREADS, SMEM_TOTAL>>>(orig, dirs, tmin, tmax,
                                                 W1, b1, W2, b2, V1, V2, c2,
                                                 (float*)d_out);
}

// round 8
// speedup vs baseline: 2.3695x; 1.1211x over previous
#include <cuda_runtime.h>
#include <cuda_bf16.h>
#include <math.h>

#define NR 8192
#define SS 128
#define GRIDF 444          // 3 CTAs/SM x 148 SMs
#define THREADS 128        // 4 warps = 1 ray per iteration

typedef unsigned int u32;

__device__ float g_base_arr[NR * 64];   // c1 + vd_enc @ V1[15:42]  (per ray)
__device__ float g_dt;

// ---------------- smem layout (bytes), per CTA ----------------
#define OFF_AH   0                 // 4 warps x 32 rows x 144B (bf16 hi)
#define OFF_AL   18432             // lo plane
#define OFF_W1H  36864             // W1^T [64n][72 bf16 stride], K pad 64
#define OFF_W1L  46080
#define OFF_W2H  55296             // W2^T [16n][72]
#define OFF_W2L  57600
#define OFF_B3H  59904             // V1[0:15]^T shifted: [64n][20 bf16 stride], k0=0
#define OFF_B3L  62464
#define OFF_B4H  65024             // V2^T [8n][72], n>=3 zero
#define OFF_B4L  66176
#define OFF_B1   67328             // b1 (64 f32)
#define OFF_B2   67584             // b2 (16 f32)
#define OFF_C2   67648             // c2 (8 f32, padded)
#define OFF_RED  67680             // 4 warp products
#define OFF_PART 67712             // 4 warps x 4 floats
#define SMEM_TOTAL 67840

static __device__ __forceinline__ u32 pk2(__nv_bfloat16 a, __nv_bfloat16 b) {
    return (u32)__bfloat16_as_ushort(a) | ((u32)__bfloat16_as_ushort(b) << 16);
}
static __device__ __forceinline__ void split2(float x, float y, u32& hi, u32& lo) {
    __nv_bfloat16 hx = __float2bfloat16(x), hy = __float2bfloat16(y);
    hi = pk2(hx, hy);
    lo = pk2(__float2bfloat16(x - __bfloat162float(hx)),
             __float2bfloat16(y - __bfloat162float(hy)));
}
static __device__ __forceinline__ void mma4(float* d, const u32* a, u32 b0, u32 b1) {
    asm volatile(
        "mma.sync.aligned.m16n8k16.row.col.f32.bf16.bf16.f32 "
        "{%0,%1,%2,%3}, {%4,%5,%6,%7}, {%8,%9}, {%0,%1,%2,%3};"
        : "+f"(d[0]), "+f"(d[1]), "+f"(d[2]), "+f"(d[3])
        : "r"(a[0]), "r"(a[1]), "r"(a[2]), "r"(a[3]), "r"(b0), "r"(b1));
}

// ---------------------------------------------------------------------------
// dt = mean(tmax - tmin) / S
// ---------------------------------------------------------------------------
__global__ __launch_bounds__(1024)
void dt_kernel(const float* __restrict__ tmin, const float* __restrict__ tmax) {
    __shared__ float red[32];
    const int t = threadIdx.x;
    const float4* a = (const float4*)tmin;
    const float4* b = (const float4*)tmax;
    float s = 0.f;
    for (int i = t; i < NR / 4; i += 1024) {
        float4 x = a[i], y = b[i];
        s += (y.x - x.x) + (y.y - x.y) + (y.z - x.z) + (y.w - x.w);
    }
#pragma unroll
    for (int o = 16; o > 0; o >>= 1) s += __shfl_down_sync(0xffffffffu, s, o);
    if ((t & 31) == 0) red[t >> 5] = s;
    __syncthreads();
    if (t < 32) {
        float v = red[t];
#pragma unroll
        for (int o = 16; o > 0; o >>= 1) v += __shfl_down_sync(0xffffffffu, v, o);
        if (t == 0) g_dt = v / (float)(NR * SS);
    }
}

// ---------------------------------------------------------------------------
// Per-ray: g_base = c1 + vd_enc @ V1[15:42]
// ---------------------------------------------------------------------------
__global__ __launch_bounds__(128)
void ray_kernel(const float* __restrict__ dirs,
                const float* __restrict__ V1, const float* __restrict__ c1) {
    const int ray = blockIdx.x * 128 + threadIdx.x;
    if (ray >= NR) return;
    const float dx = dirs[ray * 3 + 0], dy = dirs[ray * 3 + 1], dz = dirs[ray * 3 + 2];
    const float nrm = sqrtf(dx * dx + dy * dy + dz * dz) + 1e-8f;
    const float inv = 1.0f / nrm;
    const float vx = dx * inv, vy = dy * inv, vz = dz * inv;

    float v[27];
    v[0] = vx; v[1] = vy; v[2] = vz;
    {
        float sx, cx, sy, cy, sz, cz;
        sincosf(vx, &sx, &cx); sincosf(vy, &sy, &cy); sincosf(vz, &sz, &cz);
#pragma unroll
        for (int i = 0; i < 4; i++) {
            v[3 + 6 * i + 0] = sx; v[3 + 6 * i + 1] = sy; v[3 + 6 * i + 2] = sz;
            v[3 + 6 * i + 3] = cx; v[3 + 6 * i + 4] = cy; v[3 + 6 * i + 5] = cz;
            const float nsx = 2.f * sx * cx, ncx = fmaf(-2.f * sx, sx, 1.f);
            const float nsy = 2.f * sy * cy, ncy = fmaf(-2.f * sy, sy, 1.f);
            const float nsz = 2.f * sz * cz, ncz = fmaf(-2.f * sz, sz, 1.f);
            sx = nsx; cx = ncx; sy = nsy; cy = ncy; sz = nsz; cz = ncz;
        }
    }
    float acc[64];
#pragma unroll
    for (int j = 0; j < 64; j++) acc[j] = c1[j];
#pragma unroll 1
    for (int i = 0; i < 27; i++) {
        const float vi = v[i];
        const float* w = V1 + (15 + i) * 64;
#pragma unroll
        for (int j = 0; j < 64; j++) acc[j] = fmaf(vi, w[j], acc[j]);
    }
#pragma unroll
    for (int j = 0; j < 64; j++) g_base_arr[ray * 64 + j] = acc[j];
}

// ---------------------------------------------------------------------------
// Fused ray-marcher: CTA = 128 threads = 4 warps = one ray per iteration.
// Warp w handles samples w*32 .. w*32+31 (rows of the 128x* MMA tiles).
// 3 CTAs/SM -> 3 warps/SMSP; independent CTAs hide each other's stalls.
// ---------------------------------------------------------------------------
__global__ __launch_bounds__(THREADS, 3)
void fused_kernel(const float* __restrict__ orig, const float* __restrict__ dirs,
                  const float* __restrict__ tmin, const float* __restrict__ tmax,
                  const float* __restrict__ W1, const float* __restrict__ b1,
                  const float* __restrict__ W2, const float* __restrict__ b2,
                  const float* __restrict__ V1, const float* __restrict__ V2,
                  const float* __restrict__ c2, float* __restrict__ outp) {
    extern __shared__ char dsm[];
    const int tid = threadIdx.x;
    const int w = tid >> 5, lane = tid & 31, g = lane >> 2, tig = lane & 3;

    // ---------------- stage weights: split bf16 hi/lo, K-major padded ------
    for (int i = tid; i < 64 * 64; i += THREADS) {            // W1^T, K pad 64
        int n = i >> 6, k = i & 63;
        float v = (k < 63) ? W1[k * 64 + n] : 0.f;
        __nv_bfloat16 h = __float2bfloat16(v);
        *(__nv_bfloat16*)(dsm + OFF_W1H + n * 144 + k * 2) = h;
        *(__nv_bfloat16*)(dsm + OFF_W1L + n * 144 + k * 2) =
            __float2bfloat16(v - __bfloat162float(h));
    }
    for (int i = tid; i < 16 * 64; i += THREADS) {            // W2^T
        int n = i >> 6, k = i & 63;
        float v = W2[k * 16 + n];
        __nv_bfloat16 h = __float2bfloat16(v);
        *(__nv_bfloat16*)(dsm + OFF_W2H + n * 144 + k * 2) = h;
        *(__nv_bfloat16*)(dsm + OFF_W2L + n * 144 + k * 2) =
            __float2bfloat16(v - __bfloat162float(h));
    }
    for (int i = tid; i < 64 * 16; i += THREADS) {            // B3 = shifted V1[0:15]^T
        int n = i >> 4, k = i & 15;
        float v = (k >= 1) ? V1[(k - 1) * 64 + n] : 0.f;
        __nv_bfloat16 h = __float2bfloat16(v);
        *(__nv_bfloat16*)(dsm + OFF_B3H + n * 40 + k * 2) = h;
        *(__nv_bfloat16*)(dsm + OFF_B3L + n * 40 + k * 2) =
            __float2bfloat16(v - __bfloat162float(h));
    }
    for (int i = tid; i < 8 * 64; i += THREADS) {             // B4 = V2^T, n pad 8
        int n = i >> 6, k = i & 63;
        float v = (n < 3) ? V2[k * 3 + n] : 0.f;
        __nv_bfloat16 h = __float2bfloat16(v);
        *(__nv_bfloat16*)(dsm + OFF_B4H + n * 144 + k * 2) = h;
        *(__nv_bfloat16*)(dsm + OFF_B4L + n * 144 + k * 2) =
            __float2bfloat16(v - __bfloat162float(h));
    }
    for (int i = tid; i < 64; i += THREADS) ((float*)(dsm + OFF_B1))[i] = b1[i];
    if (tid < 16) ((float*)(dsm + OFF_B2))[tid] = b2[tid];
    if (tid < 8)  ((float*)(dsm + OFF_C2))[tid] = (tid < 3) ? c2[tid] : 0.f;
    __syncthreads();

    const float dtv = g_dt;
    const u32 FULL = 0xffffffffu;

    for (int ray = blockIdx.x; ray < NR; ray += GRIDF) {
        const int s = (w << 5) + lane;

        // ---------------- positional encoding, row = lane -------------------
        const float dx = dirs[ray * 3 + 0], dy = dirs[ray * 3 + 1], dz = dirs[ray * 3 + 2];
        const float t0 = tmin[ray], t1 = tmax[ray];
        const float tt = t0 + (float)s * (1.0f / (SS - 1)) * (t1 - t0);
        float enc[64];
        enc[0] = fmaf(dx, tt, orig[ray * 3 + 0]);
        enc[1] = fmaf(dy, tt, orig[ray * 3 + 1]);
        enc[2] = fmaf(dz, tt, orig[ray * 3 + 2]);
        {
            float sx, cx, sy, cy, sz, cz;
            sincosf(enc[0], &sx, &cx); sincosf(enc[1], &sy, &cy); sincosf(enc[2], &sz, &cz);
#pragma unroll
            for (int i = 0; i < 10; i++) {
                enc[3 + 6 * i + 0] = sx; enc[3 + 6 * i + 1] = sy; enc[3 + 6 * i + 2] = sz;
                enc[3 + 6 * i + 3] = cx; enc[3 + 6 * i + 4] = cy; enc[3 + 6 * i + 5] = cz;
                const float nsx = 2.f * sx * cx, ncx = fmaf(-2.f * sx, sx, 1.f);
                const float nsy = 2.f * sy * cy, ncy = fmaf(-2.f * sy, sy, 1.f);
                const float nsz = 2.f * sz * cz, ncz = fmaf(-2.f * sz, sz, 1.f);
                sx = nsx; cx = ncx; sy = nsy; cy = ncy; sz = nsz; cz = ncz;
            }
        }
        enc[63] = 0.f;
        {
            char* Ah = dsm + OFF_AH + w * 4608 + lane * 144;
            char* Al = dsm + OFF_AL + w * 4608 + lane * 144;
#pragma unroll
            for (int j8 = 0; j8 < 8; j8++) {
                u32 h0, l0, h1, l1, h2, l2, h3, l3;
                split2(enc[8 * j8 + 0], enc[8 * j8 + 1], h0, l0);
                split2(enc[8 * j8 + 2], enc[8 * j8 + 3], h1, l1);
                split2(enc[8 * j8 + 4], enc[8 * j8 + 5], h2, l2);
                split2(enc[8 * j8 + 6], enc[8 * j8 + 7], h3, l3);
                *(uint4*)(Ah + j8 * 16) = make_uint4(h0, h1, h2, h3);
                *(uint4*)(Al + j8 * 16) = make_uint4(l0, l1, l2, l3);
            }
        }
        __syncwarp();

        // ---------------- MLP1: enc(64) @ W1 -> 32x64 -----------------------
        float acc[2][8][4];
#pragma unroll
        for (int mt = 0; mt < 2; mt++)
#pragma unroll
            for (int nt = 0; nt < 8; nt++)
#pragma unroll
                for (int r = 0; r < 4; r++) acc[mt][nt][r] = 0.f;

        const char* AHb = dsm + OFF_AH + w * 4608;
        const char* ALb = dsm + OFF_AL + w * 4608;
#pragma unroll
        for (int kt = 0; kt < 4; kt++) {
            u32 AH[2][4], AL[2][4];
#pragma unroll
            for (int mt = 0; mt < 2; mt++) {
                int ab = mt * 2304 + g * 144 + kt * 32 + tig * 4;
                AH[mt][0] = *(const u32*)(AHb + ab);
                AH[mt][1] = *(const u32*)(AHb + ab + 1152);
                AH[mt][2] = *(const u32*)(AHb + ab + 16);      // k-cols +8 = +16B
                AH[mt][3] = *(const u32*)(AHb + ab + 1168);
                AL[mt][0] = *(const u32*)(ALb + ab);
                AL[mt][1] = *(const u32*)(ALb + ab + 1152);
                AL[mt][2] = *(const u32*)(ALb + ab + 16);
                AL[mt][3] = *(const u32*)(ALb + ab + 1168);
            }
#pragma unroll
            for (int nt = 0; nt < 8; nt++) {
                int bo = (nt * 8 + g) * 144 + kt * 32 + tig * 4;
                u32 bh0 = *(const u32*)(dsm + OFF_W1H + bo);
                u32 bh1 = *(const u32*)(dsm + OFF_W1H + bo + 16);
                u32 bl0 = *(const u32*)(dsm + OFF_W1L + bo);
                u32 bl1 = *(const u32*)(dsm + OFF_W1L + bo + 16);
#pragma unroll
                for (int mt = 0; mt < 2; mt++) {
                    mma4(acc[mt][nt], AH[mt], bh0, bh1);
                    mma4(acc[mt][nt], AH[mt], bl0, bl1);
                    mma4(acc[mt][nt], AL[mt], bh0, bh1);
                }
            }
        }

        // ---------------- epi1: h = relu(D + b1) -> A frags (regs) ----------
        u32 HF[2][4][4], HL[2][4][4];
#pragma unroll
        for (int kt = 0; kt < 4; kt++)
#pragma unroll
            for (int j = 0; j < 2; j++) {
                const int nt = 2 * kt + j;
                const float2 bb = *(const float2*)(dsm + OFF_B1 + (nt * 8 + tig * 2) * 4);
#pragma unroll
                for (int mt = 0; mt < 2; mt++) {
                    float v0 = fmaxf(acc[mt][nt][0] + bb.x, 0.f);
                    float v1 = fmaxf(acc[mt][nt][1] + bb.y, 0.f);
                    float v2 = fmaxf(acc[mt][nt][2] + bb.x, 0.f);
                    float v3 = fmaxf(acc[mt][nt][3] + bb.y, 0.f);
                    split2(v0, v1, HF[mt][kt][2 * j + 0], HL[mt][kt][2 * j + 0]);
                    split2(v2, v3, HF[mt][kt][2 * j + 1], HL[mt][kt][2 * j + 1]);
                }
            }

        // ---------------- MLP2: h @ W2 -> 32x16 -----------------------------
        float a2c[2][2][4];
#pragma unroll
        for (int mt = 0; mt < 2; mt++)
#pragma unroll
            for (int n2 = 0; n2 < 2; n2++)
#pragma unroll
                for (int r = 0; r < 4; r++) a2c[mt][n2][r] = 0.f;
#pragma unroll
        for (int kt = 0; kt < 4; kt++)
#pragma unroll
            for (int n2 = 0; n2 < 2; n2++) {
                int bo = (n2 * 8 + g) * 144 + kt * 32 + tig * 4;
                u32 bh0 = *(const u32*)(dsm + OFF_W2H + bo);
                u32 bh1 = *(const u32*)(dsm + OFF_W2H + bo + 16);
                u32 bl0 = *(const u32*)(dsm + OFF_W2L + bo);
                u32 bl1 = *(const u32*)(dsm + OFF_W2L + bo + 16);
#pragma unroll
                for (int mt = 0; mt < 2; mt++) {
                    mma4(a2c[mt][n2], HF[mt][kt], bh0, bh1);
                    mma4(a2c[mt][n2], HF[mt][kt], bl0, bl1);
                    mma4(a2c[mt][n2], HL[mt][kt], bh0, bh1);
                }
            }

        // ---------------- epi2: sigma raw + feat frags ----------------------
        float sgm[2][2];
        u32 FF[2][4], FL[2][4];
        {
            const float2 b20 = *(const float2*)(dsm + OFF_B2 + tig * 8);
            const float2 b21 = *(const float2*)(dsm + OFF_B2 + 32 + tig * 8);
#pragma unroll
            for (int mt = 0; mt < 2; mt++) {
                float v0 = a2c[mt][0][0] + b20.x;
                float v1 = a2c[mt][0][1] + b20.y;
                float v2 = a2c[mt][0][2] + b20.x;
                float v3 = a2c[mt][0][3] + b20.y;
                float u0 = a2c[mt][1][0] + b21.x;
                float u1 = a2c[mt][1][1] + b21.y;
                float u2 = a2c[mt][1][2] + b21.x;
                float u3 = a2c[mt][1][3] + b21.y;
                sgm[mt][0] = v0;
                sgm[mt][1] = v2;
                split2(v0, v1, FF[mt][0], FL[mt][0]);
                split2(v2, v3, FF[mt][1], FL[mt][1]);
                split2(u0, u1, FF[mt][2], FL[mt][2]);
                split2(u2, u3, FF[mt][3], FL[mt][3]);
            }
        }

        // ---------------- MLP3: feats(16) @ B3 -> 32x64 ---------------------
        float a3c[2][8][4];
#pragma unroll
        for (int mt = 0; mt < 2; mt++)
#pragma unroll
            for (int nt = 0; nt < 8; nt++)
#pragma unroll
                for (int r = 0; r < 4; r++) a3c[mt][nt][r] = 0.f;
#pragma unroll
        for (int nt = 0; nt < 8; nt++) {
            int bo = (nt * 8 + g) * 40 + tig * 4;
            u32 bh0 = *(const u32*)(dsm + OFF_B3H + bo);
            u32 bh1 = *(const u32*)(dsm + OFF_B3H + bo + 16);
            u32 bl0 = *(const u32*)(dsm + OFF_B3L + bo);
            u32 bl1 = *(const u32*)(dsm + OFF_B3L + bo + 16);
#pragma unroll
            for (int mt = 0; mt < 2; mt++) {
                mma4(a3c[mt][nt], FF[mt], bh0, bh1);
                mma4(a3c[mt][nt], FF[mt], bl0, bl1);
                mma4(a3c[mt][nt], FL[mt], bh0, bh1);
            }
        }

        // ---------------- epi3: g = relu(D + g_base) -> g frags -------------
        u32 GF[2][4][4], GL[2][4][4];
        const float* gb = g_base_arr + ray * 64;
#pragma unroll
        for (int kt = 0; kt < 4; kt++)
#pragma unroll
            for (int j = 0; j < 2; j++) {
                const int nt = 2 * kt + j;
                const float2 gv = __ldg((const float2*)(gb + nt * 8 + tig * 2));
#pragma unroll
                for (int mt = 0; mt < 2; mt++) {
                    float v0 = fmaxf(a3c[mt][nt][0] + gv.x, 0.f);
                    float v1 = fmaxf(a3c[mt][nt][1] + gv.y, 0.f);
                    float v2 = fmaxf(a3c[mt][nt][2] + gv.x, 0.f);
                    float v3 = fmaxf(a3c[mt][nt][3] + gv.y, 0.f);
                    split2(v0, v1, GF[mt][kt][2 * j + 0], GL[mt][kt][2 * j + 0]);
                    split2(v2, v3, GF[mt][kt][2 * j + 1], GL[mt][kt][2 * j + 1]);
                }
            }

        // ---------------- MLP4: g @ V2 -> 32x8 ------------------------------
        float a4[2][4];
#pragma unroll
        for (int mt = 0; mt < 2; mt++)
#pragma unroll
            for (int r = 0; r < 4; r++) a4[mt][r] = 0.f;
#pragma unroll
        for (int kt = 0; kt < 4; kt++) {
            int bo = g * 144 + kt * 32 + tig * 4;
            u32 bh0 = *(const u32*)(dsm + OFF_B4H + bo);
            u32 bh1 = *(const u32*)(dsm + OFF_B4H + bo + 16);
            u32 bl0 = *(const u32*)(dsm + OFF_B4L + bo);
            u32 bl1 = *(const u32*)(dsm + OFF_B4L + bo + 16);
#pragma unroll
            for (int mt = 0; mt < 2; mt++) {
                mma4(a4[mt], GF[mt][kt], bh0, bh1);
                mma4(a4[mt], GF[mt][kt], bl0, bl1);
                mma4(a4[mt], GL[mt][kt], bh0, bh1);
            }
        }

        // ---------------- epi4 + redistribution lane<->row ------------------
        float o0[2], o1[2], o2[2], o3[2];
        {
            const float2 cc = *(const float2*)(dsm + OFF_C2 + tig * 8);
#pragma unroll
            for (int mt = 0; mt < 2; mt++) {
                o0[mt] = a4[mt][0] + cc.x;
                o1[mt] = a4[mt][1] + cc.y;
                o2[mt] = a4[mt][2] + cc.x;
                o3[mt] = a4[mt][3] + cc.y;
            }
        }
        const int q4 = (lane & 7) * 4;
        const int selv = lane >> 3;
        float x0, x1, x2, x3;
        x0 = __shfl_sync(FULL, sgm[0][0], q4);
        x1 = __shfl_sync(FULL, sgm[0][1], q4);
        x2 = __shfl_sync(FULL, sgm[1][0], q4);
        x3 = __shfl_sync(FULL, sgm[1][1], q4);
        const float sigma = fmaxf(selv == 0 ? x0 : selv == 1 ? x1 : selv == 2 ? x2 : x3, 0.f);
        x0 = __shfl_sync(FULL, o0[0], q4);
        x1 = __shfl_sync(FULL, o2[0], q4);
        x2 = __shfl_sync(FULL, o0[1], q4);
        x3 = __shfl_sync(FULL, o2[1], q4);
        const float rv = selv == 0 ? x0 : selv == 1 ? x1 : selv == 2 ? x2 : x3;
        x0 = __shfl_sync(FULL, o1[0], q4);
        x1 = __shfl_sync(FULL, o3[0], q4);
        x2 = __shfl_sync(FULL, o1[1], q4);
        x3 = __shfl_sync(FULL, o3[1], q4);
        const float gvv = selv == 0 ? x0 : selv == 1 ? x1 : selv == 2 ? x2 : x3;
        x0 = __shfl_sync(FULL, o0[0], q4 + 1);
        x1 = __shfl_sync(FULL, o2[0], q4 + 1);
        x2 = __shfl_sync(FULL, o0[1], q4 + 1);
        x3 = __shfl_sync(FULL, o2[1], q4 + 1);
        const float bv = selv == 0 ? x0 : selv == 1 ? x1 : selv == 2 ? x2 : x3;
        const float rr = 1.f / (1.f + __expf(-rv));
        const float rg = 1.f / (1.f + __expf(-gvv));
        const float rb = 1.f / (1.f + __expf(-bv));

        // ---------------- transmittance scan --------------------------------
        {
            const float ex = __expf(-sigma * dtv);      // one_minus
            const float alpha = 1.f - ex;
            float p = ex;
#pragma unroll
            for (int o = 1; o < 32; o <<= 1) {
                float q = __shfl_up_sync(FULL, p, o);
                if (lane >= o) p *= q;
            }
            float* red = (float*)(dsm + OFF_RED);
            if (lane == 31) red[w] = p;
            __syncthreads();
            float wpre = 1.f;
#pragma unroll
            for (int k = 0; k < 3; k++)
                if (k < w) wpre *= red[k];
            const float pm1 = __shfl_up_sync(FULL, p, 1);
            const float excl = (lane == 0) ? wpre : wpre * pm1;
            const bool active = excl > 1e-4f;
            const float wgt = active ? excl * alpha : 0.f;
            float sr = wgt * rr, sg2 = wgt * rg, sb = wgt * rb;
            float ft = active ? ex : 1.f;
#pragma unroll
            for (int o = 16; o > 0; o >>= 1) {
                sr += __shfl_xor_sync(FULL, sr, o);
                sg2 += __shfl_xor_sync(FULL, sg2, o);
                sb += __shfl_xor_sync(FULL, sb, o);
                ft *= __shfl_xor_sync(FULL, ft, o);
            }
            float* part = (float*)(dsm + OFF_PART) + w * 4;
            if (lane == 0) { part[0] = sr; part[1] = sg2; part[2] = sb; part[3] = ft; }
            __syncthreads();
            if (tid == 0) {
                const float* pp = (const float*)(dsm + OFF_PART);
                float R = 0, G = 0, B = 0, T = 1.f;
#pragma unroll
                for (int k = 0; k < 4; k++) {
                    R += pp[k * 4 + 0]; G += pp[k * 4 + 1];
                    B += pp[k * 4 + 2]; T *= pp[k * 4 + 3];
                }
                outp[ray * 3 + 0] = R;
                outp[ray * 3 + 1] = G;
                outp[ray * 3 + 2] = B;
                outp[3 * NR + ray] = T;
            }
            __syncthreads();
        }
    }
}

// ---------------------------------------------------------------------------
extern "C" void kernel_launch(void* const* d_in, const int* in_sizes, int n_in,
                              void* d_out, int out_size) {
    const float* orig = (const float*)d_in[0];
    const float* dirs = (const float*)d_in[1];
    const float* tmin = (const float*)d_in[2];
    const float* tmax = (const float*)d_in[3];
    const float* W1   = (const float*)d_in[4];
    const float* b1   = (const float*)d_in[5];
    const float* W2   = (const float*)d_in[6];
    const float* b2   = (const float*)d_in[7];
    const float* V1   = (const float*)d_in[8];
    const float* c1   = (const float*)d_in[9];
    const float* V2   = (const float*)d_in[10];
    const float* c2   = (const float*)d_in[11];

    cudaFuncSetAttribute(fused_kernel, cudaFuncAttributeMaxDynamicSharedMemorySize, SMEM_TOTAL);

    dt_kernel<<<1, 1024>>>(tmin, tmax);
    ray_kernel<<<NR / 128, 128>>>(dirs, V1, c1);
    fused_kernel<<<GRIDF, THREADS, SMEM_TOTAL>>>(orig, dirs, tmin, tmax,
                                                 W1, b1, W2, b2, V1, V2, c2,
                                                 (float*)d_out);
}